// round 5
// baseline (speedup 1.0000x reference)
#include <cuda_runtime.h>

// Problem dims (fixed by the dataset)
#define B_   32
#define T_   512
#define IN_  512
#define H_   1024
#define OUT_ 512

// ---------------------------------------------------------------------------
// Device scratch (allocation-free rule: __device__ globals)
// ---------------------------------------------------------------------------
__device__ float g_xp[(size_t)B_ * T_ * H_];   // x@Wx + bx + bh, [B][T][H]
__device__ float g_hs[(size_t)B_ * T_ * H_];   // hidden states   [B][T][H]
__device__ unsigned g_bar = 0;                 // grid barrier counter

// ---------------------------------------------------------------------------
// f32x2 packed math helpers
// ---------------------------------------------------------------------------
__device__ __forceinline__ unsigned long long ffma2(unsigned long long a,
                                                    unsigned long long b,
                                                    unsigned long long c) {
    unsigned long long d;
    asm("fma.rn.f32x2 %0, %1, %2, %3;" : "=l"(d) : "l"(a), "l"(b), "l"(c));
    return d;
}
__device__ __forceinline__ unsigned long long add2(unsigned long long a,
                                                   unsigned long long b) {
    unsigned long long d;
    asm("add.rn.f32x2 %0, %1, %2;" : "=l"(d) : "l"(a), "l"(b));
    return d;
}
__device__ __forceinline__ unsigned long long splat2(float x) {
    unsigned long long d;
    asm("mov.b64 %0, {%1, %2};" : "=l"(d) : "f"(x), "f"(x));
    return d;
}
__device__ __forceinline__ float2 unpack2(unsigned long long d) {
    float2 r;
    asm("mov.b64 {%0, %1}, %2;" : "=f"(r.x), "=f"(r.y) : "l"(d));
    return r;
}

// ---------------------------------------------------------------------------
// SGEMM with bias epilogue: C = A @ Bm + b1 (+ b2)
// 128x128 tile, BK=16, 256 threads, 8x8 per-thread tile via f32x2.
// Also resets the grid-barrier counter (runs before the scan kernel).
// ---------------------------------------------------------------------------
__global__ __launch_bounds__(256, 2) void sgemm_bias_kernel(
    const float* __restrict__ A, const float* __restrict__ Bm,
    const float* __restrict__ b1p, const float* __restrict__ b2p,
    float* __restrict__ C, int M, int N, int K)
{
    if (blockIdx.x == 0 && blockIdx.y == 0 && threadIdx.x == 0) g_bar = 0u;

    __shared__ __align__(16) float As[16][128];
    __shared__ __align__(16) float Bs[16][128];

    const int tid  = threadIdx.x;
    const int row0 = blockIdx.y * 128;
    const int col0 = blockIdx.x * 128;
    const int tx   = tid & 15;
    const int ty   = tid >> 4;

    const int aRow = tid >> 2;
    const int aK4  = (tid & 3) * 4;
    const int bRow = tid >> 5;
    const int bCol = (tid & 31) * 4;

    unsigned long long acc[8][4];
#pragma unroll
    for (int i = 0; i < 8; i++)
#pragma unroll
        for (int j = 0; j < 4; j++) acc[i][j] = 0ull;

    for (int k0 = 0; k0 < K; k0 += 16) {
        float4 av0 = *(const float4*)(A + (size_t)(row0 + aRow)      * K + k0 + aK4);
        float4 av1 = *(const float4*)(A + (size_t)(row0 + aRow + 64) * K + k0 + aK4);
        float4 bv0 = *(const float4*)(Bm + (size_t)(k0 + bRow)     * N + col0 + bCol);
        float4 bv1 = *(const float4*)(Bm + (size_t)(k0 + bRow + 8) * N + col0 + bCol);

        __syncthreads();
        As[aK4 + 0][aRow] = av0.x;  As[aK4 + 1][aRow] = av0.y;
        As[aK4 + 2][aRow] = av0.z;  As[aK4 + 3][aRow] = av0.w;
        As[aK4 + 0][aRow + 64] = av1.x;  As[aK4 + 1][aRow + 64] = av1.y;
        As[aK4 + 2][aRow + 64] = av1.z;  As[aK4 + 3][aRow + 64] = av1.w;
        *(float4*)&Bs[bRow][bCol]     = bv0;
        *(float4*)&Bs[bRow + 8][bCol] = bv1;
        __syncthreads();

#pragma unroll
        for (int kk = 0; kk < 16; kk++) {
            float4 a0 = *(const float4*)&As[kk][ty * 8];
            float4 a1 = *(const float4*)&As[kk][ty * 8 + 4];
            const unsigned long long* bp =
                (const unsigned long long*)&Bs[kk][tx * 8];
            unsigned long long bq0 = bp[0], bq1 = bp[1], bq2 = bp[2], bq3 = bp[3];
            float av[8] = {a0.x, a0.y, a0.z, a0.w, a1.x, a1.y, a1.z, a1.w};
#pragma unroll
            for (int i = 0; i < 8; i++) {
                unsigned long long a2 = splat2(av[i]);
                acc[i][0] = ffma2(a2, bq0, acc[i][0]);
                acc[i][1] = ffma2(a2, bq1, acc[i][1]);
                acc[i][2] = ffma2(a2, bq2, acc[i][2]);
                acc[i][3] = ffma2(a2, bq3, acc[i][3]);
            }
        }
    }

    const int crow = row0 + ty * 8;
    const int ccol = col0 + tx * 8;
    float bsum[8];
#pragma unroll
    for (int j = 0; j < 8; j++) {
        float bv = b1p[ccol + j];
        if (b2p) bv += b2p[ccol + j];
        bsum[j] = bv;
    }
#pragma unroll
    for (int i = 0; i < 8; i++) {
        float o[8];
#pragma unroll
        for (int j4 = 0; j4 < 4; j4++) {
            float2 v = unpack2(acc[i][j4]);
            o[2 * j4]     = v.x + bsum[2 * j4];
            o[2 * j4 + 1] = v.y + bsum[2 * j4 + 1];
        }
        float4* cp = (float4*)(C + (size_t)(crow + i) * N + ccol);
        cp[0] = make_float4(o[0], o[1], o[2], o[3]);
        cp[1] = make_float4(o[4], o[5], o[6], o[7]);
    }
}

// ---------------------------------------------------------------------------
// Persistent RNN scan kernel, v3 (spill-proof).
//
// grid = 128 blocks (co-resident, 1 block/SM), block = 512 threads.
// Block owns j-columns [bx*8, bx*8+8); Wh slab (1024x8 = 32KB) smem-resident.
// Thread map: warp = ks (16 k-splits of 64 k), lane = b (0..31).
// Per step each thread:
//   - 16 named float4 regs <- its 64-element h slice (16 LDG.128 up front)
//   - fully macro-unrolled FFMA2 over 64 k x 4 j-pairs (weights via
//     uniform-address LDS.128 broadcast)
//   - 16-way cross-ks smem reduction + xp + tanh + store (tid < 128)
//   - grid barrier (nanosleep-backed poll to keep L2 atomic traffic low)
// ---------------------------------------------------------------------------
#define KSTEP(val, koff) do {                                           \
    ulonglong2 w01 = *(const ulonglong2*)(wb + ((koff) << 3));          \
    ulonglong2 w23 = *(const ulonglong2*)(wb + ((koff) << 3) + 4);      \
    unsigned long long s_ = splat2(val);                                \
    a0 = ffma2(s_, w01.x, a0); a1 = ffma2(s_, w01.y, a1);               \
    a2 = ffma2(s_, w23.x, a2); a3 = ffma2(s_, w23.y, a3); } while (0)

#define K4(v, kb) KSTEP((v).x, (kb)); KSTEP((v).y, (kb) + 1); \
                  KSTEP((v).z, (kb) + 2); KSTEP((v).w, (kb) + 3);

__global__ __launch_bounds__(512, 1) void rnn_scan_kernel(
    const float* __restrict__ h0,   // [B][H]
    const float* __restrict__ Wh,   // [H][H]
    float* __restrict__ next_h)     // [B][H]
{
    __shared__ __align__(16) float whs[H_ * 8];                   // 32KB [k][jl]
    __shared__ __align__(16) unsigned long long red[16][32][4];   // 16KB

    const int tid   = threadIdx.x;
    const int ks    = tid >> 5;       // 0..15  k-split (warp)
    const int b     = tid & 31;       // lane = batch row
    const int jbase = blockIdx.x * 8;
    const int k0    = ks * 64;

    // Load this block's Wh slab once (step-invariant).
    for (int idx = tid; idx < H_ * 8; idx += 512) {
        int k = idx >> 3, j = idx & 7;
        whs[idx] = Wh[(size_t)k * H_ + jbase + j];
    }
    __syncthreads();

    const float* wb  = whs + (k0 << 3);   // thread's weight base (warp-uniform)
    const int brow   = b * (T_ * H_);
    unsigned  target = gridDim.x;

    for (int t = 0; t < T_; t++) {
        const float* hp = ((t == 0) ? (h0 + b * H_)
                                    : (g_hs + brow + (t - 1) * H_)) + k0;

        // 16 independent LDG.128 up front (MLP=16)
        float4 v0  = *(const float4*)(hp +  0);
        float4 v1  = *(const float4*)(hp +  4);
        float4 v2  = *(const float4*)(hp +  8);
        float4 v3  = *(const float4*)(hp + 12);
        float4 v4  = *(const float4*)(hp + 16);
        float4 v5  = *(const float4*)(hp + 20);
        float4 v6  = *(const float4*)(hp + 24);
        float4 v7  = *(const float4*)(hp + 28);
        float4 v8  = *(const float4*)(hp + 32);
        float4 v9  = *(const float4*)(hp + 36);
        float4 v10 = *(const float4*)(hp + 40);
        float4 v11 = *(const float4*)(hp + 44);
        float4 v12 = *(const float4*)(hp + 48);
        float4 v13 = *(const float4*)(hp + 52);
        float4 v14 = *(const float4*)(hp + 56);
        float4 v15 = *(const float4*)(hp + 60);

        unsigned long long a0 = 0ull, a1 = 0ull, a2 = 0ull, a3 = 0ull;
        K4(v0,   0)  K4(v1,   4)  K4(v2,   8)  K4(v3,  12)
        K4(v4,  16)  K4(v5,  20)  K4(v6,  24)  K4(v7,  28)
        K4(v8,  32)  K4(v9,  36)  K4(v10, 40)  K4(v11, 44)
        K4(v12, 48)  K4(v13, 52)  K4(v14, 56)  K4(v15, 60)

        red[ks][b][0] = a0;  red[ks][b][1] = a1;
        red[ks][b][2] = a2;  red[ks][b][3] = a3;
        __syncthreads();

        if (tid < 128) {
            const int rb   = tid >> 2;   // batch row
            const int jp   = tid & 3;    // j-pair
            const int rrow = rb * (T_ * H_);
            unsigned long long xpv =
                *(const unsigned long long*)(g_xp + rrow + t * H_ + jbase + 2 * jp);

            unsigned long long s0 = add2(red[0][rb][jp],  red[1][rb][jp]);
            unsigned long long s1 = add2(red[2][rb][jp],  red[3][rb][jp]);
            unsigned long long s2 = add2(red[4][rb][jp],  red[5][rb][jp]);
            unsigned long long s3 = add2(red[6][rb][jp],  red[7][rb][jp]);
            unsigned long long s4 = add2(red[8][rb][jp],  red[9][rb][jp]);
            unsigned long long s5 = add2(red[10][rb][jp], red[11][rb][jp]);
            unsigned long long s6 = add2(red[12][rb][jp], red[13][rb][jp]);
            unsigned long long s7 = add2(red[14][rb][jp], red[15][rb][jp]);
            unsigned long long s  = add2(add2(add2(s0, s1), add2(s2, s3)),
                                         add2(add2(s4, s5), add2(s6, s7)));
            s = add2(s, xpv);

            float2 v = unpack2(s);
            v.x = tanhf(v.x);
            v.y = tanhf(v.y);
            *(float2*)(g_hs + rrow + t * H_ + jbase + 2 * jp) = v;
            if (t == T_ - 1)
                *(float2*)(next_h + rb * H_ + jbase + 2 * jp) = v;
        }

        // ---- grid barrier ----
        __threadfence();
        __syncthreads();
        if (tid == 0) {
            unsigned arrived = atomicAdd(&g_bar, 1u) + 1u;
            if (arrived < target) {
                while (*(volatile unsigned*)&g_bar < target) {
                    __nanosleep(64);
                }
            }
        }
        __syncthreads();
        target += gridDim.x;
    }
}

// ---------------------------------------------------------------------------
// kernel_launch: 4 launches, graph-capturable, default stream.
// Inputs: 0:x 1:h 2:Wx 3:bx 4:Wh 5:bh 6:W1 7:b1 8:W2 9:b2
// Output: [td0 (B*T*OUT) | td1 (B*T*OUT) | next_h (B*H)]
// ---------------------------------------------------------------------------
extern "C" void kernel_launch(void* const* d_in, const int* in_sizes, int n_in,
                              void* d_out, int out_size)
{
    (void)in_sizes; (void)n_in; (void)out_size;
    const float* x  = (const float*)d_in[0];
    const float* h  = (const float*)d_in[1];
    const float* Wx = (const float*)d_in[2];
    const float* bx = (const float*)d_in[3];
    const float* Wh = (const float*)d_in[4];
    const float* bh = (const float*)d_in[5];
    const float* W1 = (const float*)d_in[6];
    const float* b1 = (const float*)d_in[7];
    const float* W2 = (const float*)d_in[8];
    const float* b2 = (const float*)d_in[9];
    float* out = (float*)d_out;

    float* xp = nullptr;
    float* hs = nullptr;
    cudaGetSymbolAddress((void**)&xp, g_xp);
    cudaGetSymbolAddress((void**)&hs, g_hs);

    const int MT = B_ * T_;   // 16384

    // Phase 0: Xp = x @ Wx + (bx + bh).   M=16384, N=1024, K=512
    {
        dim3 grid(H_ / 128, MT / 128);
        sgemm_bias_kernel<<<grid, 256>>>(x, Wx, bx, bh, xp, MT, H_, IN_);
    }

    // Phase 1: sequential scan (persistent kernel, grid barrier per step).
    {
        float* next_h = out + (size_t)2 * MT * OUT_;
        rnn_scan_kernel<<<128, 512>>>(h, Wh, next_h);
    }

    // Phase 2: td0 = hs @ W1 + b1 ; td1 = hs @ W2 + b2.  M=16384, N=512, K=1024
    {
        dim3 grid(OUT_ / 128, MT / 128);
        sgemm_bias_kernel<<<grid, 256>>>(hs, W1, b1, nullptr, out, MT, OUT_, H_);
        sgemm_bias_kernel<<<grid, 256>>>(hs, W2, b2, nullptr,
                                         out + (size_t)MT * OUT_, MT, OUT_, H_);
    }
}

// round 6
// speedup vs baseline: 1.5137x; 1.5137x over previous
#include <cuda_runtime.h>

// Problem dims (fixed by the dataset)
#define B_   32
#define T_   512
#define IN_  512
#define H_   1024
#define OUT_ 512

// ---------------------------------------------------------------------------
// Device scratch (allocation-free rule: __device__ globals)
// ---------------------------------------------------------------------------
__device__ float g_xp[(size_t)B_ * T_ * H_];   // x@Wx + bx + bh, [B][T][H]
__device__ float g_hs[(size_t)B_ * T_ * H_];   // hidden states   [B][T][H]
__device__ float g_hx[2][H_ * B_];             // h exchange ping-pong, [j][b]
__device__ unsigned g_bar = 0;                 // grid barrier counter

// ---------------------------------------------------------------------------
// f32x2 packed math helpers
// ---------------------------------------------------------------------------
__device__ __forceinline__ unsigned long long ffma2(unsigned long long a,
                                                    unsigned long long b,
                                                    unsigned long long c) {
    unsigned long long d;
    asm("fma.rn.f32x2 %0, %1, %2, %3;" : "=l"(d) : "l"(a), "l"(b), "l"(c));
    return d;
}
__device__ __forceinline__ unsigned long long add2(unsigned long long a,
                                                   unsigned long long b) {
    unsigned long long d;
    asm("add.rn.f32x2 %0, %1, %2;" : "=l"(d) : "l"(a), "l"(b));
    return d;
}
__device__ __forceinline__ unsigned long long splat2(float x) {
    unsigned long long d;
    asm("mov.b64 %0, {%1, %2};" : "=l"(d) : "f"(x), "f"(x));
    return d;
}
__device__ __forceinline__ float2 unpack2(unsigned long long d) {
    float2 r;
    asm("mov.b64 {%0, %1}, %2;" : "=f"(r.x), "=f"(r.y) : "l"(d));
    return r;
}

// ---------------------------------------------------------------------------
// SGEMM with bias epilogue: C = A @ Bm + b1 (+ b2)
// 128x128 tile, BK=16, 256 threads, 8x8 per-thread tile via f32x2.
// Also resets the grid-barrier counter (runs before the scan kernel).
// ---------------------------------------------------------------------------
__global__ __launch_bounds__(256, 2) void sgemm_bias_kernel(
    const float* __restrict__ A, const float* __restrict__ Bm,
    const float* __restrict__ b1p, const float* __restrict__ b2p,
    float* __restrict__ C, int M, int N, int K)
{
    if (blockIdx.x == 0 && blockIdx.y == 0 && threadIdx.x == 0) g_bar = 0u;

    __shared__ __align__(16) float As[16][128];
    __shared__ __align__(16) float Bs[16][128];

    const int tid  = threadIdx.x;
    const int row0 = blockIdx.y * 128;
    const int col0 = blockIdx.x * 128;
    const int tx   = tid & 15;
    const int ty   = tid >> 4;

    const int aRow = tid >> 2;
    const int aK4  = (tid & 3) * 4;
    const int bRow = tid >> 5;
    const int bCol = (tid & 31) * 4;

    unsigned long long acc[8][4];
#pragma unroll
    for (int i = 0; i < 8; i++)
#pragma unroll
        for (int j = 0; j < 4; j++) acc[i][j] = 0ull;

    for (int k0 = 0; k0 < K; k0 += 16) {
        float4 av0 = *(const float4*)(A + (size_t)(row0 + aRow)      * K + k0 + aK4);
        float4 av1 = *(const float4*)(A + (size_t)(row0 + aRow + 64) * K + k0 + aK4);
        float4 bv0 = *(const float4*)(Bm + (size_t)(k0 + bRow)     * N + col0 + bCol);
        float4 bv1 = *(const float4*)(Bm + (size_t)(k0 + bRow + 8) * N + col0 + bCol);

        __syncthreads();
        As[aK4 + 0][aRow] = av0.x;  As[aK4 + 1][aRow] = av0.y;
        As[aK4 + 2][aRow] = av0.z;  As[aK4 + 3][aRow] = av0.w;
        As[aK4 + 0][aRow + 64] = av1.x;  As[aK4 + 1][aRow + 64] = av1.y;
        As[aK4 + 2][aRow + 64] = av1.z;  As[aK4 + 3][aRow + 64] = av1.w;
        *(float4*)&Bs[bRow][bCol]     = bv0;
        *(float4*)&Bs[bRow + 8][bCol] = bv1;
        __syncthreads();

#pragma unroll
        for (int kk = 0; kk < 16; kk++) {
            float4 a0 = *(const float4*)&As[kk][ty * 8];
            float4 a1 = *(const float4*)&As[kk][ty * 8 + 4];
            const unsigned long long* bp =
                (const unsigned long long*)&Bs[kk][tx * 8];
            unsigned long long bq0 = bp[0], bq1 = bp[1], bq2 = bp[2], bq3 = bp[3];
            float av[8] = {a0.x, a0.y, a0.z, a0.w, a1.x, a1.y, a1.z, a1.w};
#pragma unroll
            for (int i = 0; i < 8; i++) {
                unsigned long long a2 = splat2(av[i]);
                acc[i][0] = ffma2(a2, bq0, acc[i][0]);
                acc[i][1] = ffma2(a2, bq1, acc[i][1]);
                acc[i][2] = ffma2(a2, bq2, acc[i][2]);
                acc[i][3] = ffma2(a2, bq3, acc[i][3]);
            }
        }
    }

    const int crow = row0 + ty * 8;
    const int ccol = col0 + tx * 8;
    float bsum[8];
#pragma unroll
    for (int j = 0; j < 8; j++) {
        float bv = b1p[ccol + j];
        if (b2p) bv += b2p[ccol + j];
        bsum[j] = bv;
    }
#pragma unroll
    for (int i = 0; i < 8; i++) {
        float o[8];
#pragma unroll
        for (int j4 = 0; j4 < 4; j4++) {
            float2 v = unpack2(acc[i][j4]);
            o[2 * j4]     = v.x + bsum[2 * j4];
            o[2 * j4 + 1] = v.y + bsum[2 * j4 + 1];
        }
        float4* cp = (float4*)(C + (size_t)(crow + i) * N + ccol);
        cp[0] = make_float4(o[0], o[1], o[2], o[3]);
        cp[1] = make_float4(o[4], o[5], o[6], o[7]);
    }
}

// ---------------------------------------------------------------------------
// h0 transpose: [B][H] -> g_hx[1] in [j][b] layout.  (scan step t=0 reads
// buffer (t+1)&1 = 1)
// ---------------------------------------------------------------------------
__global__ void h0_transpose_kernel(const float* __restrict__ h0)
{
    int idx = blockIdx.x * 256 + threadIdx.x;   // 32768 total
    int b = idx >> 10;          // 0..31
    int j = idx & 1023;         // 0..1023
    g_hx[1][j * B_ + b] = h0[idx];
}

// ---------------------------------------------------------------------------
// Persistent RNN scan kernel, v4 (coalesced h exchange).
//
// grid = 128 blocks (co-resident, 1 block/SM), block = 512 threads.
// Block owns j-columns [bx*8, bx*8+8); Wh slab (1024x8 = 32KB) in DYNAMIC
// smem (static red[] uses 16KB; 48KB total).
// Thread map: warp = ks (16 k-splits of 64 k), lane = b (0..31).
// h exchange lives in g_hx[2][H][B] ([j][b] layout, 256KB, L2-resident):
//   - reads:  hx[k*32 + b] -> lanes consecutive -> 1 line per warp-load
//   - writes: reduction thread (jp=tid>>5, rb=tid&31) stores coalesced
// xp for the step is prefetched at the top (DRAM latency hidden under FMA).
// Barrier: red.release.gpu arrival + ld.acquire.gpu poll.
// ---------------------------------------------------------------------------
__global__ __launch_bounds__(512, 1) void rnn_scan_kernel(
    const float* __restrict__ Wh,   // [H][H]
    float* __restrict__ next_h)     // [B][H]
{
    extern __shared__ __align__(16) float whs[];                  // 32KB [k][jl]
    __shared__ __align__(16) unsigned long long red[16][4][32];   // 16KB

    const int tid   = threadIdx.x;
    const int ks    = tid >> 5;       // 0..15  k-split (warp)
    const int b     = tid & 31;       // lane = batch row
    const int jbase = blockIdx.x * 8;
    const int k0    = ks * 64;

    // Load this block's Wh slab once (step-invariant).
    for (int idx = tid; idx < H_ * 8; idx += 512) {
        int k = idx >> 3, j = idx & 7;
        whs[idx] = Wh[(size_t)k * H_ + jbase + j];
    }
    __syncthreads();

    const float* wb = whs + (k0 << 3);    // warp-uniform weight base
    // reduction-role indices (valid when tid < 128)
    const int jp = tid >> 5;              // 0..3 (== ks for tid<128)
    const int rb = tid & 31;              // batch row
    const int j0 = jbase + 2 * jp;

    unsigned* bar_ptr = &g_bar;
    unsigned  target  = gridDim.x;

    for (int t = 0; t < T_; t++) {
        const float* hx = g_hx[(t + 1) & 1] + k0 * B_ + b;   // [k][b] slice
        float*       hw = g_hx[t & 1];

        // prefetch xp for this step (reduction threads only use it later)
        unsigned long long xpv = 0ull;
        if (tid < 128)
            xpv = *(const unsigned long long*)
                  (g_xp + (size_t)rb * (T_ * H_) + t * H_ + j0);

        unsigned long long a0 = 0ull, a1 = 0ull, a2 = 0ull, a3 = 0ull;
#pragma unroll
        for (int c = 0; c < 4; c++) {
            float hv[16];
#pragma unroll
            for (int i = 0; i < 16; i++)
                hv[i] = hx[(c * 16 + i) * B_];
#pragma unroll
            for (int i = 0; i < 16; i++) {
                const int k = c * 16 + i;
                ulonglong2 w01 = *(const ulonglong2*)(wb + (k << 3));
                ulonglong2 w23 = *(const ulonglong2*)(wb + (k << 3) + 4);
                unsigned long long s_ = splat2(hv[i]);
                a0 = ffma2(s_, w01.x, a0);  a1 = ffma2(s_, w01.y, a1);
                a2 = ffma2(s_, w23.x, a2);  a3 = ffma2(s_, w23.y, a3);
            }
        }

        // partials -> smem   (layout [ks][jp][b]: conflict-free both ways)
        red[ks][0][b] = a0;  red[ks][1][b] = a1;
        red[ks][2][b] = a2;  red[ks][3][b] = a3;
        __syncthreads();

        if (tid < 128) {
            unsigned long long s0 = add2(red[0][jp][rb],  red[1][jp][rb]);
            unsigned long long s1 = add2(red[2][jp][rb],  red[3][jp][rb]);
            unsigned long long s2 = add2(red[4][jp][rb],  red[5][jp][rb]);
            unsigned long long s3 = add2(red[6][jp][rb],  red[7][jp][rb]);
            unsigned long long s4 = add2(red[8][jp][rb],  red[9][jp][rb]);
            unsigned long long s5 = add2(red[10][jp][rb], red[11][jp][rb]);
            unsigned long long s6 = add2(red[12][jp][rb], red[13][jp][rb]);
            unsigned long long s7 = add2(red[14][jp][rb], red[15][jp][rb]);
            unsigned long long s  = add2(add2(add2(s0, s1), add2(s2, s3)),
                                         add2(add2(s4, s5), add2(s6, s7)));
            s = add2(s, xpv);

            float2 v = unpack2(s);
            v.x = tanhf(v.x);
            v.y = tanhf(v.y);

            // coalesced exchange-buffer store ([j][b], lanes = rb consecutive)
            hw[j0 * B_ + rb]       = v.x;
            hw[(j0 + 1) * B_ + rb] = v.y;
            // row-major history for the phase-2 GEMMs
            *(float2*)(g_hs + (size_t)rb * (T_ * H_) + t * H_ + j0) = v;
            if (t == T_ - 1)
                *(float2*)(next_h + rb * H_ + j0) = v;
        }

        // ---- grid barrier (release arrival, acquire poll) ----
        __syncthreads();
        if (tid == 0) {
            asm volatile("red.release.gpu.global.add.u32 [%0], %1;"
                         :: "l"(bar_ptr), "r"(1u) : "memory");
            unsigned v;
            while (1) {
                asm volatile("ld.acquire.gpu.global.u32 %0, [%1];"
                             : "=r"(v) : "l"(bar_ptr) : "memory");
                if (v >= target) break;
                __nanosleep(32);
            }
        }
        __syncthreads();
        target += gridDim.x;
    }
}

// ---------------------------------------------------------------------------
// kernel_launch: 5 launches, graph-capturable, default stream.
// Inputs: 0:x 1:h 2:Wx 3:bx 4:Wh 5:bh 6:W1 7:b1 8:W2 9:b2
// Output: [td0 (B*T*OUT) | td1 (B*T*OUT) | next_h (B*H)]
// ---------------------------------------------------------------------------
extern "C" void kernel_launch(void* const* d_in, const int* in_sizes, int n_in,
                              void* d_out, int out_size)
{
    (void)in_sizes; (void)n_in; (void)out_size;
    const float* x  = (const float*)d_in[0];
    const float* h  = (const float*)d_in[1];
    const float* Wx = (const float*)d_in[2];
    const float* bx = (const float*)d_in[3];
    const float* Wh = (const float*)d_in[4];
    const float* bh = (const float*)d_in[5];
    const float* W1 = (const float*)d_in[6];
    const float* b1 = (const float*)d_in[7];
    const float* W2 = (const float*)d_in[8];
    const float* b2 = (const float*)d_in[9];
    float* out = (float*)d_out;

    float* xp = nullptr;
    float* hs = nullptr;
    cudaGetSymbolAddress((void**)&xp, g_xp);
    cudaGetSymbolAddress((void**)&hs, g_hs);

    const int MT = B_ * T_;   // 16384

    // Phase 0: Xp = x @ Wx + (bx + bh).   M=16384, N=1024, K=512
    {
        dim3 grid(H_ / 128, MT / 128);
        sgemm_bias_kernel<<<grid, 256>>>(x, Wx, bx, bh, xp, MT, H_, IN_);
    }

    // Phase 0b: transpose h0 into the [j][b] exchange buffer.
    h0_transpose_kernel<<<(B_ * H_) / 256, 256>>>(h);

    // Phase 1: sequential scan (persistent kernel, grid barrier per step).
    {
        float* next_h = out + (size_t)2 * MT * OUT_;
        rnn_scan_kernel<<<128, 512, H_ * 8 * sizeof(float)>>>(Wh, next_h);
    }

    // Phase 2: td0 = hs @ W1 + b1 ; td1 = hs @ W2 + b2.  M=16384, N=512, K=1024
    {
        dim3 grid(OUT_ / 128, MT / 128);
        sgemm_bias_kernel<<<grid, 256>>>(hs, W1, b1, nullptr, out, MT, OUT_, H_);
        sgemm_bias_kernel<<<grid, 256>>>(hs, W2, b2, nullptr,
                                         out + (size_t)MT * OUT_, MT, OUT_, H_);
    }
}